// round 7
// baseline (speedup 1.0000x reference)
#include <cuda_runtime.h>

// Problem: B=4, D=64, K=32, N=8192. Total floats = 2,097,152 = 524288 float4.
#define Kk 32
#define Dk 64
#define TPB 256
#define GRIDA 2048           // kernel A: 1 float4 per thread; block = 256 float4
                             // blk = bd*8 + chunk  (8 blocks per (b,d) plane)

typedef unsigned long long u64;

__device__ float g_partial[GRIDA];   // per-block sum of E (deterministic)

__device__ __forceinline__ float ex2(float x) {
    float y; asm("ex2.approx.f32 %0, %1;" : "=f"(y) : "f"(x)); return y;
}
__device__ __forceinline__ u64 pk(float lo, float hi) {
    u64 r; asm("mov.b64 %0, {%1,%2};" : "=l"(r) : "f"(lo), "f"(hi)); return r;
}
__device__ __forceinline__ void upk(float& lo, float& hi, u64 v) {
    asm("mov.b64 {%0,%1}, %2;" : "=f"(lo), "=f"(hi) : "l"(v));
}
__device__ __forceinline__ u64 add2(u64 a, u64 b) {
    u64 r; asm("add.rn.f32x2 %0, %1, %2;" : "=l"(r) : "l"(a), "l"(b)); return r;
}
__device__ __forceinline__ u64 mul2(u64 a, u64 b) {
    u64 r; asm("mul.rn.f32x2 %0, %1, %2;" : "=l"(r) : "l"(a), "l"(b)); return r;
}
__device__ __forceinline__ u64 fma2(u64 a, u64 b, u64 c) {
    u64 r; asm("fma.rn.f32x2 %0, %1, %2, %3;" : "=l"(r) : "l"(a), "l"(b), "l"(c)); return r;
}

// ---- Kernel A: E (unscaled) + per-block partial sums ----
__global__ void __launch_bounds__(TPB)
k_encode(const float* __restrict__ X, const float* __restrict__ cw,
         const float* __restrict__ sc, float* __restrict__ out)
{
    // Per-k constants (d block-uniform, compile-time smem addressing):
    //   arg = slx*x^2 + p1*x + p0;  slx = scale*log2e, p1 = -2c*slx, p0 = c^2*slx
    __shared__ u64 s_p1[Kk], s_p0[Kk], s_sl[Kk], s_nc[Kk];
    __shared__ float s_red[TPB / 32];

    const int t   = threadIdx.x;
    const int blk = blockIdx.x;
    const int d   = (blk >> 3) & 63;

    if (t < Kk) {
        const float c   = cw[t * Dk + d];
        const float slx = sc[t * Dk + d] * 1.4426950408889634f;
        s_p1[t] = pk(-2.0f * c * slx, -2.0f * c * slx);
        s_p0[t] = pk(c * c * slx, c * c * slx);
        s_sl[t] = pk(slx, slx);
        s_nc[t] = pk(-c, -c);
    }
    __syncthreads();

    const float4 v = ((const float4*)X)[blk * TPB + t];
    const u64 xa = pk(v.x, v.y), xb = pk(v.z, v.w);
    const u64 xxa = mul2(xa, xa), xxb = mul2(xb, xb);
    u64 dena = 0ull, denb = 0ull, wa = 0ull, wb = 0ull;

    #pragma unroll 8
    for (int k = 0; k < Kk; k++) {
        const u64 p1 = s_p1[k], p0 = s_p0[k], sl = s_sl[k], nc = s_nc[k];
        u64 a0 = fma2(sl, xxa, fma2(p1, xa, p0));   // arg <= 0
        u64 a1 = fma2(sl, xxb, fma2(p1, xb, p0));
        float l0, h0, l1, h1;
        upk(l0, h0, a0);
        upk(l1, h1, a1);
        const u64 e0 = pk(ex2(l0), ex2(h0));
        const u64 e1 = pk(ex2(l1), ex2(h1));
        dena = add2(dena, e0);  wa = fma2(e0, nc, wa);   // w = sum e*(-c)
        denb = add2(denb, e1);  wb = fma2(e1, nc, wb);
    }

    const u64 na = fma2(xa, dena, wa);   // num = x*den - sum(e*c)
    const u64 nb = fma2(xb, denb, wb);
    float n0, n1, n2, n3, d0, d1, d2, d3;
    upk(n0, n1, na); upk(n2, n3, nb);
    upk(d0, d1, dena); upk(d2, d3, denb);
    float4 o;
    o.x = __fdividef(n0, d0);
    o.y = __fdividef(n1, d1);
    o.z = __fdividef(n2, d2);
    o.w = __fdividef(n3, d3);
    ((float4*)out)[blk * TPB + t] = o;   // unscaled E; kernel B rescales

    float ssum = (o.x + o.y) + (o.z + o.w);
    #pragma unroll
    for (int off = 16; off > 0; off >>= 1)
        ssum += __shfl_xor_sync(0xffffffffu, ssum, off);
    if ((t & 31) == 0) s_red[t >> 5] = ssum;
    __syncthreads();
    if (t == 0) {
        float s = 0.f;
        #pragma unroll
        for (int w = 0; w < TPB / 32; w++) s += s_red[w];
        g_partial[blk] = s;
    }
}

// ---- Kernel B: gamma (redundant per block) + scale + relu ----
__global__ void __launch_bounds__(TPB)
k_scale(const float* __restrict__ fw, const float* __restrict__ fb,
        float* __restrict__ out)
{
    __shared__ float s_eg[Dk];
    __shared__ float s_g1;

    const int t   = threadIdx.x;
    const int blk = blockIdx.x;
    const int bd  = blk >> 3;
    const int d   = bd & 63;
    const int b   = bd >> 6;

    if (t < Dk) {
        const float* gp = &g_partial[(b * Dk + t) * 8];
        float s = 0.f;
        #pragma unroll
        for (int r = 0; r < 8; r++) s += __ldcg(gp + r);
        s_eg[t] = s * (1.0f / Kk);
    }
    __syncthreads();
    if (t < 32) {
        const float* fwr = fw + d * Dk;
        float acc = s_eg[t] * __ldg(fwr + t) + s_eg[t + 32] * __ldg(fwr + t + 32);
        #pragma unroll
        for (int off = 16; off > 0; off >>= 1)
            acc += __shfl_xor_sync(0xffffffffu, acc, off);
        if (t == 0)
            s_g1 = 1.f + 1.f / (1.f + __expf(-(acc + __ldg(fb + d))));  // 1+sigmoid
    }
    __syncthreads();

    const float g = s_g1;
    float4* op = (float4*)out + blk * TPB + t;
    float4 o;
    o.x = __ldcg(&op->x); o.y = __ldcg(&op->y);
    o.z = __ldcg(&op->z); o.w = __ldcg(&op->w);
    o.x = fmaxf(o.x * g, 0.f); o.y = fmaxf(o.y * g, 0.f);
    o.z = fmaxf(o.z * g, 0.f); o.w = fmaxf(o.w * g, 0.f);
    *op = o;
}

extern "C" void kernel_launch(void* const* d_in, const int* in_sizes, int n_in,
                              void* d_out, int out_size)
{
    const float* X   = (const float*)d_in[0];  // (B,D,T,H,W)
    const float* cw  = (const float*)d_in[1];  // (K,D)
    const float* sc  = (const float*)d_in[2];  // (K,D)
    const float* fcw = (const float*)d_in[3];  // (D,D)
    const float* fcb = (const float*)d_in[4];  // (D,)
    float* out = (float*)d_out;

    k_encode<<<GRIDA, TPB>>>(X, cw, sc, out);
    k_scale<<<GRIDA, TPB>>>(fcw, fcb, out);
}